// round 6
// baseline (speedup 1.0000x reference)
#include <cuda_runtime.h>

// Problem dims (fixed by the reference setup)
#define NB 4      // batch
#define NQ 16     // queries used (of 20)
#define NQP 20    // queries stored in btn_dec
#define NT 8      // t
#define NHW 256   // h*w
#define HWT 8     // hw positions per block
#define ND 512    // d = G*C
#define NG 8      // heads
#define NC 64     // channels per head
#define NF 512    // btn_features

__device__ __forceinline__ float dot4(float4 a, float4 b) {
    return fmaf(a.x, b.x, fmaf(a.y, b.y, fmaf(a.z, b.z, a.w * b.w)));
}

__device__ __forceinline__ void ffma2(unsigned long long& d,
                                      unsigned long long a,
                                      unsigned long long b) {
    asm("fma.rn.f32x2 %0, %1, %2, %0;" : "+l"(d) : "l"(a), "l"(b));
}

// ---------------------------------------------------------------------------
// Fused kernel. Grid: 1024 blocks = (b:4) x (t:8) x (hw-tile:32), 128 thr.
//
// Phase A (warp-per-hw, proven in R4/R5 K1): each of 4 warps computes 2 hw
// rows; full 512-float enc row via 4 CONTIGUOUS LDG.128, dec rows likewise
// (L1-hot), per-lane dot4 partials, shfl_xor reduce per 16-lane half.
// Scores written PRE-DUPLICATED as (s,s) pairs into smem [q][hwl][16].
//
// Phase B (proven in R5 K2): thread = f4 column, W+bias in regs, loop over
// 128 rows; per row: 4 broadcast LDS.128, 16 FFMA2, 1 streaming STG.128.
// No scratch gmem round-trip, no second launch.
// ---------------------------------------------------------------------------
__global__ void __launch_bounds__(128, 8) heatmap_fused(
    const float* __restrict__ dec,   // (4, 20, 8, 512)
    const float* __restrict__ enc,   // (4, 8, 256, 512)
    const float* __restrict__ Wm,    // (8, 512)
    const float* __restrict__ bias,  // (512,)
    float* __restrict__ out)         // (4, 16, 8, 256, 512)
{
    __shared__ float sc_s[NQ * HWT * 16];   // 8 KB: [q][hwl][2*g + dup]

    const int tid  = threadIdx.x;
    const int bid  = blockIdx.x;
    const int hwt  = bid & 31;         // hw tile (8 positions)
    const int t    = (bid >> 5) & 7;
    const int b    = bid >> 8;

    // ---------------- Phase A: scores -> smem ----------------
    {
        const int lane = tid & 31;
        const int warp = tid >> 5;     // 0..3, each covers hwl = 2*warp+{0,1}

        const int half  = lane >> 4;   // head parity
        const int lh    = lane & 15;
        const int j_sel = lh >> 1;     // which partial this lane owns
        const int dup   = lane & 1;    // element of the (s,s) pair
        const bool active = lh < 8;
        const int woff  = 4 * j_sel + 2 * half + dup;

#pragma unroll
        for (int i = 0; i < 2; i++) {
            const int hwl = warp * 2 + i;
            const float4* enc4 = reinterpret_cast<const float4*>(enc)
                + ((size_t)((b * NT + t) * NHW + hwt * HWT + hwl)) * 128;
            float4 e0 = enc4[lane];
            float4 e1 = enc4[lane + 32];
            float4 e2 = enc4[lane + 64];
            float4 e3 = enc4[lane + 96];

            float* srow = sc_s + hwl * 16 + woff;   // + q*(HWT*16)

#pragma unroll
            for (int q = 0; q < NQ; q++) {
                const float4* dec4 = reinterpret_cast<const float4*>(dec)
                    + ((size_t)((b * NQP + q) * NT + t)) * 128;
                float p0 = dot4(e0, dec4[lane]);
                float p1 = dot4(e1, dec4[lane + 32]);
                float p2 = dot4(e2, dec4[lane + 64]);
                float p3 = dot4(e3, dec4[lane + 96]);
#pragma unroll
                for (int m = 1; m <= 8; m <<= 1) {
                    p0 += __shfl_xor_sync(0xffffffffu, p0, m);
                    p1 += __shfl_xor_sync(0xffffffffu, p1, m);
                    p2 += __shfl_xor_sync(0xffffffffu, p2, m);
                    p3 += __shfl_xor_sync(0xffffffffu, p3, m);
                }
                float s = (j_sel == 0) ? p0 : (j_sel == 1) ? p1
                        : (j_sel == 2) ? p2 : p3;
                if (active) srow[q * (HWT * 16)] = s;
            }
        }
    }

    // W/bias regs loaded before the sync to overlap with phase-A tail
    const int f4 = tid;
    const unsigned long long* W2 = reinterpret_cast<const unsigned long long*>(Wm);
    unsigned long long wreg[NG][2];
#pragma unroll
    for (int g = 0; g < NG; g++) {
        wreg[g][0] = W2[g * 256 + f4 * 2];
        wreg[g][1] = W2[g * 256 + f4 * 2 + 1];
    }
    const unsigned long long* B2 = reinterpret_cast<const unsigned long long*>(bias);
    const unsigned long long bb0 = B2[f4 * 2];
    const unsigned long long bb1 = B2[f4 * 2 + 1];

    __syncthreads();

    // ---------------- Phase B: projection + relu, stream out ----------------
    {
        const ulonglong2* sc = reinterpret_cast<const ulonglong2*>(sc_s);
        // out float4 index: (((b*16+q)*8+t)*256 + hwt*8+hwl)*128 + f4
        float4* out4 = reinterpret_cast<float4*>(out)
            + ((size_t)(b * NQ * NT + t) * NHW + hwt * HWT) * 128 + f4;
        // q stride (float4): 8*256*128 = 262144 ; hwl stride: 128

#pragma unroll 4
        for (int r = 0; r < NQ * HWT; r++) {      // r = q*8 + hwl
            ulonglong2 u01 = sc[r * 4 + 0];       // (s0,s0),(s1,s1)
            ulonglong2 u23 = sc[r * 4 + 1];
            ulonglong2 u45 = sc[r * 4 + 2];
            ulonglong2 u67 = sc[r * 4 + 3];

            unsigned long long a0 = bb0, a1 = bb1;
            ffma2(a0, u01.x, wreg[0][0]); ffma2(a1, u01.x, wreg[0][1]);
            ffma2(a0, u01.y, wreg[1][0]); ffma2(a1, u01.y, wreg[1][1]);
            ffma2(a0, u23.x, wreg[2][0]); ffma2(a1, u23.x, wreg[2][1]);
            ffma2(a0, u23.y, wreg[3][0]); ffma2(a1, u23.y, wreg[3][1]);
            ffma2(a0, u45.x, wreg[4][0]); ffma2(a1, u45.x, wreg[4][1]);
            ffma2(a0, u45.y, wreg[5][0]); ffma2(a1, u45.y, wreg[5][1]);
            ffma2(a0, u67.x, wreg[6][0]); ffma2(a1, u67.x, wreg[6][1]);
            ffma2(a0, u67.y, wreg[7][0]); ffma2(a1, u67.y, wreg[7][1]);

            float4 res;
            asm("mov.b64 {%0, %1}, %2;" : "=f"(res.x), "=f"(res.y) : "l"(a0));
            asm("mov.b64 {%0, %1}, %2;" : "=f"(res.z), "=f"(res.w) : "l"(a1));
            res.x = fmaxf(res.x, 0.f);
            res.y = fmaxf(res.y, 0.f);
            res.z = fmaxf(res.z, 0.f);
            res.w = fmaxf(res.w, 0.f);

            const int q   = r >> 3;
            const int hwl = r & 7;
            __stcs(&out4[(size_t)q * 262144 + hwl * 128], res);
        }
    }
}

extern "C" void kernel_launch(void* const* d_in, const int* in_sizes, int n_in,
                              void* d_out, int out_size)
{
    const float* dec  = (const float*)d_in[0];  // (4,20,8,512)
    const float* enc  = (const float*)d_in[1];  // (4,8,16,16,512)
    const float* Wm   = (const float*)d_in[2];  // (8,512)
    const float* bias = (const float*)d_in[3];  // (512,)
    float* out = (float*)d_out;                 // (4,16,8,16,16,512)

    heatmap_fused<<<NB * NT * (NHW / HWT), 128>>>(dec, enc, Wm, bias, out);
}

// round 7
// speedup vs baseline: 2.1694x; 2.1694x over previous
#include <cuda_runtime.h>

// Problem dims (fixed by the reference setup)
#define NB 4      // batch
#define NQ 16     // queries used (of 20)
#define NQP 20    // queries stored in btn_dec
#define NT 8      // t
#define NHW 256   // h*w
#define HWT 32    // hw positions per K1 block
#define NG 8      // heads
#define NF 512    // btn_features
#define NROWS (NB * NQ * NT * NHW)   // 131072 output rows

// Scratch: scores duplicated as (s,s) pairs: [row][2*g + {0,1}] -> 16 floats/row, 8 MB
__device__ float g_scores2[NROWS * 2 * NG];

__device__ __forceinline__ void ffma2(unsigned long long& d,
                                      unsigned long long a,
                                      unsigned long long b) {
    asm("fma.rn.f32x2 %0, %1, %2, %0;" : "+l"(d) : "l"(a), "l"(b));
}
__device__ __forceinline__ unsigned long long pack2(float lo, float hi) {
    unsigned long long r;
    asm("mov.b64 %0, {%1, %2};" : "=l"(r) : "f"(lo), "f"(hi));
    return r;
}
__device__ __forceinline__ void unpack2(unsigned long long v, float& lo, float& hi) {
    asm("mov.b64 {%0, %1}, %2;" : "=f"(lo), "=f"(hi) : "l"(v));
}

// Swizzled float4-index within a 512-float row: head g, chunk c4 (0..15).
// The (c4+g)&15 skew makes the 8 g's of one warp-phase hit 8 distinct
// bank-quads -> conflict-free LDS.128 for both the g-parallel reads and the
// broadcast dec reads.
__device__ __forceinline__ int sw_idx(int g, int c4) {
    return g * 16 + ((c4 + g) & 15);
}

// ---------------------------------------------------------------------------
// K1 (shfl-free): grid 256 = (b:4) x (t:8) x (hw-tile:8), 256 threads,
// 96KB dynamic smem (enc tile 64KB + dec tile 32KB, both g-skew swizzled).
// thread = (hw:32, g:8); accumulates all 16 q in packed f32x2 registers.
// Per (q,c4): 1 broadcast-friendly LDS.128 + 2 FFMA2. No shuffles at all.
// Epilogue: s = lo+hi, write (s,s) pair; warp stores 256B contiguous per q.
// ---------------------------------------------------------------------------
__global__ void __launch_bounds__(256) scores_kernel(
    const float* __restrict__ dec,   // (4, 20, 8, 512)
    const float* __restrict__ enc)   // (4, 8, 256, 512)
{
    extern __shared__ char smem_raw[];
    ulonglong2* enc_s = reinterpret_cast<ulonglong2*>(smem_raw);           // 4096 x 16B
    ulonglong2* dec_s = reinterpret_cast<ulonglong2*>(smem_raw + 65536);   // 2048 x 16B

    const int tid = threadIdx.x;
    const int bid = blockIdx.x;
    const int hwt = bid & 7;
    const int t   = (bid >> 3) & 7;
    const int b   = bid >> 6;

    // ---- stage enc tile: 32 hw rows x 128 float4, swizzled ----
    {
        const ulonglong2* encg = reinterpret_cast<const ulonglong2*>(enc)
            + ((size_t)((b * NT + t) * NHW + hwt * HWT)) * 128;
#pragma unroll
        for (int k = 0; k < 16; k++) {
            int i = tid + k * 256;           // 0..4095
            int hwl = i >> 7;
            int j   = i & 127;
            enc_s[hwl * 128 + sw_idx(j >> 4, j & 15)] = encg[i];
        }
    }
    // ---- stage dec tile: 16 q rows x 128 float4, swizzled ----
    {
#pragma unroll
        for (int k = 0; k < 8; k++) {
            int i = tid + k * 256;           // 0..2047
            int q = i >> 7;
            int j = i & 127;
            const ulonglong2* decg = reinterpret_cast<const ulonglong2*>(dec)
                + ((size_t)((b * NQP + q) * NT + t)) * 128;
            dec_s[q * 128 + sw_idx(j >> 4, j & 15)] = decg[j];
        }
    }
    __syncthreads();

    // ---- compute: thread = (hw, g), all 16 q in packed accumulators ----
    const int g   = tid & 7;
    const int hwl = tid >> 3;

    unsigned long long acc[NQ];
#pragma unroll
    for (int q = 0; q < NQ; q++) acc[q] = 0ull;

    const ulonglong2* erow = enc_s + hwl * 128;

#pragma unroll 2
    for (int c4 = 0; c4 < 16; c4++) {
        const int cc = sw_idx(g, c4);
        ulonglong2 e = erow[cc];
#pragma unroll
        for (int q = 0; q < NQ; q++) {
            ulonglong2 d = dec_s[q * 128 + cc];
            ffma2(acc[q], e.x, d.x);
            ffma2(acc[q], e.y, d.y);
        }
    }

    // ---- epilogue: horizontal add, duplicate, store (s,s) pairs ----
    const int hw_global = hwt * HWT + hwl;
    unsigned long long* gs2 = reinterpret_cast<unsigned long long*>(g_scores2);
#pragma unroll
    for (int q = 0; q < NQ; q++) {
        float lo, hi;
        unpack2(acc[q], lo, hi);
        float s = lo + hi;
        size_t row = ((size_t)(b * NQ + q) * NT + t) * NHW + hw_global;
        gs2[row * 8 + g] = pack2(s, s);
    }
}

// ---------------------------------------------------------------------------
// K2 (unchanged from R5, proven 45us / DRAM 61%): thread = f4 column,
// block stages its 4KB of scores to smem once; per row: 4 broadcast LDS.128,
// 16 FFMA2, 1 streaming STG.128.
// ---------------------------------------------------------------------------
#define RPB 64   // rows per block

__global__ void __launch_bounds__(128, 8) proj_kernel(
    const float* __restrict__ Wm,     // (8, 512)
    const float* __restrict__ bias,   // (512,)
    float* __restrict__ out)          // (131072, 512)
{
    __shared__ float sc_s[RPB * 16];  // 4 KB

    const int f4 = threadIdx.x;
    const size_t row0 = (size_t)blockIdx.x * RPB;

    {
        const float4* gsc = reinterpret_cast<const float4*>(g_scores2 + row0 * 16);
        float4* ssc = reinterpret_cast<float4*>(sc_s);
        ssc[f4]       = gsc[f4];
        ssc[f4 + 128] = gsc[f4 + 128];
    }

    const unsigned long long* W2 = reinterpret_cast<const unsigned long long*>(Wm);
    unsigned long long wreg[NG][2];
#pragma unroll
    for (int g = 0; g < NG; g++) {
        wreg[g][0] = W2[g * 256 + f4 * 2];
        wreg[g][1] = W2[g * 256 + f4 * 2 + 1];
    }
    const unsigned long long* B2 = reinterpret_cast<const unsigned long long*>(bias);
    const unsigned long long bb0 = B2[f4 * 2];
    const unsigned long long bb1 = B2[f4 * 2 + 1];

    __syncthreads();

    const ulonglong2* sc = reinterpret_cast<const ulonglong2*>(sc_s);
    float4* out4 = reinterpret_cast<float4*>(out) + row0 * 128 + f4;

#pragma unroll 4
    for (int r = 0; r < RPB; r++) {
        ulonglong2 u01 = sc[r * 4 + 0];   // (s0,s0),(s1,s1)
        ulonglong2 u23 = sc[r * 4 + 1];
        ulonglong2 u45 = sc[r * 4 + 2];
        ulonglong2 u67 = sc[r * 4 + 3];

        unsigned long long a0 = bb0, a1 = bb1;
        ffma2(a0, u01.x, wreg[0][0]); ffma2(a1, u01.x, wreg[0][1]);
        ffma2(a0, u01.y, wreg[1][0]); ffma2(a1, u01.y, wreg[1][1]);
        ffma2(a0, u23.x, wreg[2][0]); ffma2(a1, u23.x, wreg[2][1]);
        ffma2(a0, u23.y, wreg[3][0]); ffma2(a1, u23.y, wreg[3][1]);
        ffma2(a0, u45.x, wreg[4][0]); ffma2(a1, u45.x, wreg[4][1]);
        ffma2(a0, u45.y, wreg[5][0]); ffma2(a1, u45.y, wreg[5][1]);
        ffma2(a0, u67.x, wreg[6][0]); ffma2(a1, u67.x, wreg[6][1]);
        ffma2(a0, u67.y, wreg[7][0]); ffma2(a1, u67.y, wreg[7][1]);

        float4 res;
        asm("mov.b64 {%0, %1}, %2;" : "=f"(res.x), "=f"(res.y) : "l"(a0));
        asm("mov.b64 {%0, %1}, %2;" : "=f"(res.z), "=f"(res.w) : "l"(a1));
        res.x = fmaxf(res.x, 0.f);
        res.y = fmaxf(res.y, 0.f);
        res.z = fmaxf(res.z, 0.f);
        res.w = fmaxf(res.w, 0.f);

        __stcs(&out4[r * 128], res);
    }
}

extern "C" void kernel_launch(void* const* d_in, const int* in_sizes, int n_in,
                              void* d_out, int out_size)
{
    const float* dec  = (const float*)d_in[0];  // (4,20,8,512)
    const float* enc  = (const float*)d_in[1];  // (4,8,16,16,512)
    const float* Wm   = (const float*)d_in[2];  // (8,512)
    const float* bias = (const float*)d_in[3];  // (512,)
    float* out = (float*)d_out;                 // (4,16,8,16,16,512)

    const int k1_smem = 96 * 1024;
    cudaFuncSetAttribute(scores_kernel,
                         cudaFuncAttributeMaxDynamicSharedMemorySize, k1_smem);

    // K1: 256 blocks = (b:4)x(t:8)x(hwtile:8), 256 threads, 96KB smem
    scores_kernel<<<NB * NT * (NHW / HWT), 256, k1_smem>>>(dec, enc);

    // K2: 131072 rows / 64 rows-per-block = 2048 blocks x 128 threads
    proj_kernel<<<NROWS / RPB, 128>>>(Wm, bias, out);
}

// round 8
// speedup vs baseline: 2.4444x; 1.1268x over previous
#include <cuda_runtime.h>

// Problem dims (fixed by the reference setup)
#define NB 4      // batch
#define NQ 16     // queries used (of 20)
#define NQP 20    // queries stored in btn_dec
#define NT 8      // t
#define NHW 256   // h*w
#define HWT 8     // hw positions per block
#define NG 8      // heads
#define NF 512    // btn_features

__device__ __forceinline__ void ffma2(unsigned long long& d,
                                      unsigned long long a,
                                      unsigned long long b) {
    asm("fma.rn.f32x2 %0, %1, %2, %0;" : "+l"(d) : "l"(a), "l"(b));
}
__device__ __forceinline__ unsigned long long pack2(float lo, float hi) {
    unsigned long long r;
    asm("mov.b64 %0, {%1, %2};" : "=l"(r) : "f"(lo), "f"(hi));
    return r;
}
__device__ __forceinline__ void unpack2(unsigned long long v, float& lo, float& hi) {
    asm("mov.b64 {%0, %1}, %2;" : "=f"(lo), "=f"(hi) : "l"(v));
}

// Swizzled float4-index within a 512-float row: head g, chunk c4 (0..15).
// (c4+g)&15 skew -> the 8 g's of one warp phase hit 8 distinct 16B bank
// quads: conflict-free enc reads, single-wavefront broadcast dec reads.
__device__ __forceinline__ int sw_idx(int g, int c4) {
    return g * 16 + ((c4 + g) & 15);
}

// ---------------------------------------------------------------------------
// Fully fused kernel. Grid: 1024 blocks = (b:4) x (t:8) x (hwtile:32),
// 128 threads, 56KB dynamic smem -> 4 blocks/SM.
//
// Phase A (shfl-free, proven in R7 K1): stage enc tile (8hw x 512, 16KB) and
// dec tile (16q x 512, 32KB) swizzled; thread = (qh:2, hw:8, g:8) accumulates
// 8 q in packed f32x2 regs; per (q,c4): 1 broadcast LDS + 2 FFMA2.
// Scores written PRE-DUPLICATED as (s,s) 64-bit words into 8KB smem.
//
// Phase B (proven in R5 K2): thread = f4 column, W+bias in regs; per row:
// 4 broadcast LDS.128, 16 FFMA2, 1 streaming STG.128. 128 rows.
// No scratch gmem, single launch; phase A of one block overlaps phase B
// store streams of its 3 SM-cohabitants.
// ---------------------------------------------------------------------------
__global__ void __launch_bounds__(128, 4) heatmap_fused(
    const float* __restrict__ dec,   // (4, 20, 8, 512)
    const float* __restrict__ enc,   // (4, 8, 256, 512)
    const float* __restrict__ Wm,    // (8, 512)
    const float* __restrict__ bias,  // (512,)
    float* __restrict__ out)         // (4, 16, 8, 256, 512)
{
    extern __shared__ char smem_raw[];
    ulonglong2* enc_s = reinterpret_cast<ulonglong2*>(smem_raw);            // 16 KB
    ulonglong2* dec_s = reinterpret_cast<ulonglong2*>(smem_raw + 16384);    // 32 KB
    float*      sc_s  = reinterpret_cast<float*>(smem_raw + 49152);         //  8 KB

    const int tid = threadIdx.x;
    const int bid = blockIdx.x;
    const int hwt = bid & 31;
    const int t   = (bid >> 5) & 7;
    const int b   = bid >> 8;

    // ---- stage enc tile: 8 hw rows x 128 float4, swizzled ----
    {
        const ulonglong2* encg = reinterpret_cast<const ulonglong2*>(enc)
            + ((size_t)((b * NT + t) * NHW + hwt * HWT)) * 128;
#pragma unroll
        for (int k = 0; k < 8; k++) {
            int i = tid + k * 128;           // 0..1023
            int hwl = i >> 7;
            int j   = i & 127;
            enc_s[hwl * 128 + sw_idx(j >> 4, j & 15)] = encg[i];
        }
    }
    // ---- stage dec tile: 16 q rows x 128 float4, swizzled ----
    {
#pragma unroll
        for (int k = 0; k < 16; k++) {
            int i = tid + k * 128;           // 0..2047
            int q = i >> 7;
            int j = i & 127;
            const ulonglong2* decg = reinterpret_cast<const ulonglong2*>(dec)
                + ((size_t)((b * NQP + q) * NT + t)) * 128;
            dec_s[q * 128 + sw_idx(j >> 4, j & 15)] = decg[j];
        }
    }
    __syncthreads();

    // ---- phase A compute: thread = (qh, hw, g), 8 q packed accumulators ----
    {
        const int g   = tid & 7;
        const int hwl = (tid >> 3) & 7;
        const int qh  = tid >> 6;

        unsigned long long acc[8];
#pragma unroll
        for (int q = 0; q < 8; q++) acc[q] = 0ull;

        const ulonglong2* erow = enc_s + hwl * 128;
        const ulonglong2* drow = dec_s + qh * 8 * 128;

#pragma unroll 2
        for (int c4 = 0; c4 < 16; c4++) {
            const int cc = sw_idx(g, c4);
            ulonglong2 e = erow[cc];
#pragma unroll
            for (int qq = 0; qq < 8; qq++) {
                ulonglong2 d = drow[qq * 128 + cc];
                ffma2(acc[qq], e.x, d.x);
                ffma2(acc[qq], e.y, d.y);
            }
        }

        // scores pre-duplicated: row r = q*8+hwl, 16 floats [2g+dup]
        unsigned long long* scp = reinterpret_cast<unsigned long long*>(sc_s);
#pragma unroll
        for (int qq = 0; qq < 8; qq++) {
            float lo, hi;
            unpack2(acc[qq], lo, hi);
            float s = lo + hi;
            int r = (qh * 8 + qq) * HWT + hwl;
            scp[r * 8 + g] = pack2(s, s);
        }
    }

    // W/bias regs loaded before the sync to overlap with phase-A tail
    const int f4 = tid;
    const unsigned long long* W2 = reinterpret_cast<const unsigned long long*>(Wm);
    unsigned long long wreg[NG][2];
#pragma unroll
    for (int g = 0; g < NG; g++) {
        wreg[g][0] = W2[g * 256 + f4 * 2];
        wreg[g][1] = W2[g * 256 + f4 * 2 + 1];
    }
    const unsigned long long* B2 = reinterpret_cast<const unsigned long long*>(bias);
    const unsigned long long bb0 = B2[f4 * 2];
    const unsigned long long bb1 = B2[f4 * 2 + 1];

    __syncthreads();

    // ---- phase B: projection + relu, stream out ----
    {
        const ulonglong2* sc = reinterpret_cast<const ulonglong2*>(sc_s);
        float4* out4 = reinterpret_cast<float4*>(out)
            + ((size_t)(b * NQ * NT + t) * NHW + hwt * HWT) * 128 + f4;
        // q stride (float4): 8*256*128 = 262144 ; hwl stride: 128

#pragma unroll 4
        for (int r = 0; r < NQ * HWT; r++) {      // r = q*8 + hwl
            ulonglong2 u01 = sc[r * 4 + 0];       // (s0,s0),(s1,s1)
            ulonglong2 u23 = sc[r * 4 + 1];
            ulonglong2 u45 = sc[r * 4 + 2];
            ulonglong2 u67 = sc[r * 4 + 3];

            unsigned long long a0 = bb0, a1 = bb1;
            ffma2(a0, u01.x, wreg[0][0]); ffma2(a1, u01.x, wreg[0][1]);
            ffma2(a0, u01.y, wreg[1][0]); ffma2(a1, u01.y, wreg[1][1]);
            ffma2(a0, u23.x, wreg[2][0]); ffma2(a1, u23.x, wreg[2][1]);
            ffma2(a0, u23.y, wreg[3][0]); ffma2(a1, u23.y, wreg[3][1]);
            ffma2(a0, u45.x, wreg[4][0]); ffma2(a1, u45.x, wreg[4][1]);
            ffma2(a0, u45.y, wreg[5][0]); ffma2(a1, u45.y, wreg[5][1]);
            ffma2(a0, u67.x, wreg[6][0]); ffma2(a1, u67.x, wreg[6][1]);
            ffma2(a0, u67.y, wreg[7][0]); ffma2(a1, u67.y, wreg[7][1]);

            float4 res;
            asm("mov.b64 {%0, %1}, %2;" : "=f"(res.x), "=f"(res.y) : "l"(a0));
            asm("mov.b64 {%0, %1}, %2;" : "=f"(res.z), "=f"(res.w) : "l"(a1));
            res.x = fmaxf(res.x, 0.f);
            res.y = fmaxf(res.y, 0.f);
            res.z = fmaxf(res.z, 0.f);
            res.w = fmaxf(res.w, 0.f);

            const int q   = r >> 3;
            const int hwl = r & 7;
            __stcs(&out4[(size_t)q * 262144 + hwl * 128], res);
        }
    }
}

extern "C" void kernel_launch(void* const* d_in, const int* in_sizes, int n_in,
                              void* d_out, int out_size)
{
    const float* dec  = (const float*)d_in[0];  // (4,20,8,512)
    const float* enc  = (const float*)d_in[1];  // (4,8,16,16,512)
    const float* Wm   = (const float*)d_in[2];  // (8,512)
    const float* bias = (const float*)d_in[3];  // (512,)
    float* out = (float*)d_out;                 // (4,16,8,16,16,512)

    const int smem = 56 * 1024;
    cudaFuncSetAttribute(heatmap_fused,
                         cudaFuncAttributeMaxDynamicSharedMemorySize, smem);

    heatmap_fused<<<NB * NT * (NHW / HWT), 128, smem>>>(dec, enc, Wm, bias, out);
}

// round 9
// speedup vs baseline: 2.5090x; 1.0264x over previous
#include <cuda_runtime.h>

// Problem dims (fixed by the reference setup)
#define NB 4      // batch
#define NQ 16     // queries used (of 20)
#define NQP 20    // queries stored in btn_dec
#define NT 8      // t
#define NHW 256   // h*w
#define HWT 8     // hw positions per block
#define QT 8      // q positions per block
#define NG 8      // heads
#define NF 512    // btn_features

__device__ __forceinline__ void ffma2(unsigned long long& d,
                                      unsigned long long a,
                                      unsigned long long b) {
    asm("fma.rn.f32x2 %0, %1, %2, %0;" : "+l"(d) : "l"(a), "l"(b));
}
__device__ __forceinline__ unsigned long long pack2(float lo, float hi) {
    unsigned long long r;
    asm("mov.b64 %0, {%1, %2};" : "=l"(r) : "f"(lo), "f"(hi));
    return r;
}
__device__ __forceinline__ void unpack2(unsigned long long v, float& lo, float& hi) {
    asm("mov.b64 {%0, %1}, %2;" : "=f"(lo), "=f"(hi) : "l"(v));
}

// Swizzled float4-index within a 512-float row: head g, chunk c4 (0..15).
// (c4+g)&15 skew -> conflict-free g-parallel reads, 1-wavefront broadcasts.
__device__ __forceinline__ int sw_idx(int g, int c4) {
    return g * 16 + ((c4 + g) & 15);
}

// ---------------------------------------------------------------------------
// Fused kernel, q-split for residency. Grid: 2048 blocks =
// (b:4) x (t:8) x (hwtile:32) x (qh:2), 128 threads, 36KB smem -> 6 blk/SM.
// qh is the LOWEST grid bit so paired blocks share the enc tile via L2.
//
// Phase A: stage enc (8hw x 512, 16KB) + dec (8q x 512, 16KB) swizzled;
// thread = (qsub:2, hw:8, g:8) accumulates 4 q in packed f32x2 regs.
// Scores pre-duplicated as (s,s) words -> 4KB smem.
//
// Phase B: thread = f4 column; W+bias in regs; 64 rows; per row:
// 4 broadcast LDS.128, 16 FFMA2, 1 streaming STG.128.
// ---------------------------------------------------------------------------
__global__ void __launch_bounds__(128, 6) heatmap_fused(
    const float* __restrict__ dec,   // (4, 20, 8, 512)
    const float* __restrict__ enc,   // (4, 8, 256, 512)
    const float* __restrict__ Wm,    // (8, 512)
    const float* __restrict__ bias,  // (512,)
    float* __restrict__ out)         // (4, 16, 8, 256, 512)
{
    extern __shared__ char smem_raw[];
    ulonglong2* enc_s = reinterpret_cast<ulonglong2*>(smem_raw);            // 16 KB
    ulonglong2* dec_s = reinterpret_cast<ulonglong2*>(smem_raw + 16384);    // 16 KB
    float*      sc_s  = reinterpret_cast<float*>(smem_raw + 32768);         //  4 KB

    const int tid = threadIdx.x;
    const int bid = blockIdx.x;
    const int qh  = bid & 1;            // q half: q0 = qh*8
    const int hwt = (bid >> 1) & 31;
    const int t   = (bid >> 6) & 7;
    const int b   = bid >> 9;

    // ---- stage enc tile: 8 hw rows x 128 float4, swizzled ----
    {
        const ulonglong2* encg = reinterpret_cast<const ulonglong2*>(enc)
            + ((size_t)((b * NT + t) * NHW + hwt * HWT)) * 128;
#pragma unroll
        for (int k = 0; k < 8; k++) {
            int i = tid + k * 128;           // 0..1023
            int hwl = i >> 7;
            int j   = i & 127;
            enc_s[hwl * 128 + sw_idx(j >> 4, j & 15)] = encg[i];
        }
    }
    // ---- stage dec tile: 8 q rows x 128 float4, swizzled ----
    {
#pragma unroll
        for (int k = 0; k < 8; k++) {
            int i = tid + k * 128;           // 0..1023
            int q = i >> 7;                  // local q 0..7
            int j = i & 127;
            const ulonglong2* decg = reinterpret_cast<const ulonglong2*>(dec)
                + ((size_t)((b * NQP + qh * QT + q) * NT + t)) * 128;
            dec_s[q * 128 + sw_idx(j >> 4, j & 15)] = decg[j];
        }
    }
    __syncthreads();

    // ---- phase A compute: thread = (qsub, hw, g), 4 q packed accumulators --
    {
        const int g    = tid & 7;
        const int hwl  = (tid >> 3) & 7;
        const int qsub = tid >> 6;           // 0/1 -> local q = qsub*4 + qq

        unsigned long long acc[4];
#pragma unroll
        for (int q = 0; q < 4; q++) acc[q] = 0ull;

        const ulonglong2* erow = enc_s + hwl * 128;
        const ulonglong2* drow = dec_s + qsub * 4 * 128;

#pragma unroll 4
        for (int c4 = 0; c4 < 16; c4++) {
            const int cc = sw_idx(g, c4);
            ulonglong2 e = erow[cc];
#pragma unroll
            for (int qq = 0; qq < 4; qq++) {
                ulonglong2 d = drow[qq * 128 + cc];
                ffma2(acc[qq], e.x, d.x);
                ffma2(acc[qq], e.y, d.y);
            }
        }

        // scores pre-duplicated: row r = qlocal*8 + hwl, 16 floats [2g+dup]
        unsigned long long* scp = reinterpret_cast<unsigned long long*>(sc_s);
#pragma unroll
        for (int qq = 0; qq < 4; qq++) {
            float lo, hi;
            unpack2(acc[qq], lo, hi);
            float s = lo + hi;
            int r = (qsub * 4 + qq) * HWT + hwl;
            scp[r * 8 + g] = pack2(s, s);
        }
    }

    // W/bias regs loaded before the sync to overlap with phase-A tail
    const int f4 = tid;
    const unsigned long long* W2 = reinterpret_cast<const unsigned long long*>(Wm);
    unsigned long long wreg[NG][2];
#pragma unroll
    for (int g = 0; g < NG; g++) {
        wreg[g][0] = W2[g * 256 + f4 * 2];
        wreg[g][1] = W2[g * 256 + f4 * 2 + 1];
    }
    const unsigned long long* B2 = reinterpret_cast<const unsigned long long*>(bias);
    const unsigned long long bb0 = B2[f4 * 2];
    const unsigned long long bb1 = B2[f4 * 2 + 1];

    __syncthreads();

    // ---- phase B: projection + relu, stream out ----
    {
        const ulonglong2* sc = reinterpret_cast<const ulonglong2*>(sc_s);
        // out float4 base: (((b*16 + qh*8)*8+t)*256 + hwt*8)*128 + f4
        float4* out4 = reinterpret_cast<float4*>(out)
            + ((size_t)((b * NQ + qh * QT) * NT + t) * NHW + hwt * HWT) * 128 + f4;
        // local q stride (float4): 8*256*128 = 262144 ; hwl stride: 128

#pragma unroll 4
        for (int r = 0; r < QT * HWT; r++) {      // r = qlocal*8 + hwl
            ulonglong2 u01 = sc[r * 4 + 0];       // (s0,s0),(s1,s1)
            ulonglong2 u23 = sc[r * 4 + 1];
            ulonglong2 u45 = sc[r * 4 + 2];
            ulonglong2 u67 = sc[r * 4 + 3];

            unsigned long long a0 = bb0, a1 = bb1;
            ffma2(a0, u01.x, wreg[0][0]); ffma2(a1, u01.x, wreg[0][1]);
            ffma2(a0, u01.y, wreg[1][0]); ffma2(a1, u01.y, wreg[1][1]);
            ffma2(a0, u23.x, wreg[2][0]); ffma2(a1, u23.x, wreg[2][1]);
            ffma2(a0, u23.y, wreg[3][0]); ffma2(a1, u23.y, wreg[3][1]);
            ffma2(a0, u45.x, wreg[4][0]); ffma2(a1, u45.x, wreg[4][1]);
            ffma2(a0, u45.y, wreg[5][0]); ffma2(a1, u45.y, wreg[5][1]);
            ffma2(a0, u67.x, wreg[6][0]); ffma2(a1, u67.x, wreg[6][1]);
            ffma2(a0, u67.y, wreg[7][0]); ffma2(a1, u67.y, wreg[7][1]);

            float4 res;
            asm("mov.b64 {%0, %1}, %2;" : "=f"(res.x), "=f"(res.y) : "l"(a0));
            asm("mov.b64 {%0, %1}, %2;" : "=f"(res.z), "=f"(res.w) : "l"(a1));
            res.x = fmaxf(res.x, 0.f);
            res.y = fmaxf(res.y, 0.f);
            res.z = fmaxf(res.z, 0.f);
            res.w = fmaxf(res.w, 0.f);

            const int q   = r >> 3;
            const int hwl = r & 7;
            __stcs(&out4[(size_t)q * 262144 + hwl * 128], res);
        }
    }
}

extern "C" void kernel_launch(void* const* d_in, const int* in_sizes, int n_in,
                              void* d_out, int out_size)
{
    const float* dec  = (const float*)d_in[0];  // (4,20,8,512)
    const float* enc  = (const float*)d_in[1];  // (4,8,16,16,512)
    const float* Wm   = (const float*)d_in[2];  // (8,512)
    const float* bias = (const float*)d_in[3];  // (512,)
    float* out = (float*)d_out;                 // (4,16,8,16,16,512)

    const int smem = 36 * 1024;
    cudaFuncSetAttribute(heatmap_fused,
                         cudaFuncAttributeMaxDynamicSharedMemorySize, smem);

    // 2048 blocks = (b:4)x(t:8)x(hwtile:32)x(qh:2)
    heatmap_fused<<<NB * NT * (NHW / HWT) * 2, 128, smem>>>(dec, enc, Wm, bias, out);
}

// round 10
// speedup vs baseline: 2.5123x; 1.0013x over previous
#include <cuda_runtime.h>

// Problem dims (fixed by the reference setup)
#define NB 4      // batch
#define NQ 16     // queries used (of 20)
#define NQP 20    // queries stored in btn_dec
#define NT 8      // t
#define NHW 256   // h*w
#define HWT 16    // hw positions per block
#define QT 8      // q positions per block
#define NG 8      // heads
#define NF 512    // btn_features

__device__ __forceinline__ void ffma2(unsigned long long& d,
                                      unsigned long long a,
                                      unsigned long long b) {
    asm("fma.rn.f32x2 %0, %1, %2, %0;" : "+l"(d) : "l"(a), "l"(b));
}
__device__ __forceinline__ unsigned long long pack2(float lo, float hi) {
    unsigned long long r;
    asm("mov.b64 %0, {%1, %2};" : "=l"(r) : "f"(lo), "f"(hi));
    return r;
}
__device__ __forceinline__ void unpack2(unsigned long long v, float& lo, float& hi) {
    asm("mov.b64 {%0, %1}, %2;" : "=f"(lo), "=f"(hi) : "l"(v));
}

// Swizzled float4-index within a 512-float row: head g, chunk c4 (0..15).
// (c4+g)&15 skew -> the 8 g's of one warp phase hit 8 distinct 16B bank
// quads: conflict-free g-parallel reads; dec reads have only 8 distinct
// addresses per warp (128B bank data -> 1-cyc wavefront).
__device__ __forceinline__ int sw_idx(int g, int c4) {
    return g * 16 + ((c4 + g) & 15);
}

// ---------------------------------------------------------------------------
// Fused kernel, L1-wavefront-optimized. Grid: 1024 blocks =
// (b:4) x (t:8) x (hwtile:16) x (qh:2), 128 threads, 52KB smem -> 4 blk/SM.
//
// Phase A: stage enc (16hw x 512, 32KB) + dec (8q x 512, 16KB) swizzled;
// thread = (hwl:16, g:8) accumulates 8 q in packed f32x2 regs.
// Per c4: 1 enc LDS (4cyc) + 8 dec LDS (1cyc each) -> 2x fewer L1 cycles
// per score than R9. Scores stored DE-DUPLICATED (8 floats/row, 4KB).
//
// Phase B: thread = f4 column; W+bias in regs; 128 rows; per row:
// 2 broadcast LDS.128, 8 pack MOV64 (ALU pipe), 16 FFMA2, 1 streaming STG.
// ---------------------------------------------------------------------------
__global__ void __launch_bounds__(128, 4) heatmap_fused(
    const float* __restrict__ dec,   // (4, 20, 8, 512)
    const float* __restrict__ enc,   // (4, 8, 256, 512)
    const float* __restrict__ Wm,    // (8, 512)
    const float* __restrict__ bias,  // (512,)
    float* __restrict__ out)         // (4, 16, 8, 256, 512)
{
    extern __shared__ char smem_raw[];
    ulonglong2* enc_s = reinterpret_cast<ulonglong2*>(smem_raw);            // 32 KB
    ulonglong2* dec_s = reinterpret_cast<ulonglong2*>(smem_raw + 32768);    // 16 KB
    float*      sc_s  = reinterpret_cast<float*>(smem_raw + 49152);         //  4 KB

    const int tid = threadIdx.x;
    const int bid = blockIdx.x;
    const int qh  = bid & 1;             // q half: q0 = qh*8
    const int hwt = (bid >> 1) & 15;     // hw tile (16 positions)
    const int t   = (bid >> 5) & 7;
    const int b   = bid >> 8;

    // ---- stage enc tile: 16 hw rows x 128 float4, swizzled ----
    {
        const ulonglong2* encg = reinterpret_cast<const ulonglong2*>(enc)
            + ((size_t)((b * NT + t) * NHW + hwt * HWT)) * 128;
#pragma unroll
        for (int k = 0; k < 16; k++) {
            int i = tid + k * 128;           // 0..2047
            int hwl = i >> 7;
            int j   = i & 127;
            enc_s[hwl * 128 + sw_idx(j >> 4, j & 15)] = encg[i];
        }
    }
    // ---- stage dec tile: 8 q rows x 128 float4, swizzled ----
    {
#pragma unroll
        for (int k = 0; k < 8; k++) {
            int i = tid + k * 128;           // 0..1023
            int q = i >> 7;                  // local q 0..7
            int j = i & 127;
            const ulonglong2* decg = reinterpret_cast<const ulonglong2*>(dec)
                + ((size_t)((b * NQP + qh * QT + q) * NT + t)) * 128;
            dec_s[q * 128 + sw_idx(j >> 4, j & 15)] = decg[j];
        }
    }
    __syncthreads();

    // ---- phase A compute: thread = (hwl, g), 8 q packed accumulators ----
    {
        const int g   = tid & 7;
        const int hwl = tid >> 3;            // 0..15

        unsigned long long acc[QT];
#pragma unroll
        for (int q = 0; q < QT; q++) acc[q] = 0ull;

        const ulonglong2* erow = enc_s + hwl * 128;

#pragma unroll 4
        for (int c4 = 0; c4 < 16; c4++) {
            const int cc = sw_idx(g, c4);
            ulonglong2 e = erow[cc];
#pragma unroll
            for (int q = 0; q < QT; q++) {
                ulonglong2 d = dec_s[q * 128 + cc];
                ffma2(acc[q], e.x, d.x);
                ffma2(acc[q], e.y, d.y);
            }
        }

        // de-duplicated scores: row r = qlocal*16 + hwl, 8 floats [g]
        // banks: (r*8+g)&31 = ((hwl&3)*8+g) -> all 32 distinct, conflict-free
#pragma unroll
        for (int q = 0; q < QT; q++) {
            float lo, hi;
            unpack2(acc[q], lo, hi);
            sc_s[(q * HWT + hwl) * NG + g] = lo + hi;
        }
    }

    // W/bias regs loaded before the sync to overlap with phase-A tail
    const int f4 = tid;
    const unsigned long long* W2 = reinterpret_cast<const unsigned long long*>(Wm);
    unsigned long long wreg[NG][2];
#pragma unroll
    for (int g = 0; g < NG; g++) {
        wreg[g][0] = W2[g * 256 + f4 * 2];
        wreg[g][1] = W2[g * 256 + f4 * 2 + 1];
    }
    const unsigned long long* B2 = reinterpret_cast<const unsigned long long*>(bias);
    const unsigned long long bb0 = B2[f4 * 2];
    const unsigned long long bb1 = B2[f4 * 2 + 1];

    __syncthreads();

    // ---- phase B: projection + relu, stream out ----
    {
        const float4* scf = reinterpret_cast<const float4*>(sc_s);
        // out float4 base: (((b*16 + qh*8)*8+t)*256 + hwt*16)*128 + f4
        float4* out4 = reinterpret_cast<float4*>(out)
            + ((size_t)((b * NQ + qh * QT) * NT + t) * NHW + hwt * HWT) * 128 + f4;
        // local q stride (float4): 8*256*128 = 262144 ; hwl stride: 128

#pragma unroll 4
        for (int r = 0; r < QT * HWT; r++) {   // r = qlocal*16 + hwl
            float4 sA = scf[r * 2 + 0];        // s0..s3
            float4 sB = scf[r * 2 + 1];        // s4..s7

            unsigned long long a0 = bb0, a1 = bb1;
            unsigned long long sp;
            sp = pack2(sA.x, sA.x); ffma2(a0, sp, wreg[0][0]); ffma2(a1, sp, wreg[0][1]);
            sp = pack2(sA.y, sA.y); ffma2(a0, sp, wreg[1][0]); ffma2(a1, sp, wreg[1][1]);
            sp = pack2(sA.z, sA.z); ffma2(a0, sp, wreg[2][0]); ffma2(a1, sp, wreg[2][1]);
            sp = pack2(sA.w, sA.w); ffma2(a0, sp, wreg[3][0]); ffma2(a1, sp, wreg[3][1]);
            sp = pack2(sB.x, sB.x); ffma2(a0, sp, wreg[4][0]); ffma2(a1, sp, wreg[4][1]);
            sp = pack2(sB.y, sB.y); ffma2(a0, sp, wreg[5][0]); ffma2(a1, sp, wreg[5][1]);
            sp = pack2(sB.z, sB.z); ffma2(a0, sp, wreg[6][0]); ffma2(a1, sp, wreg[6][1]);
            sp = pack2(sB.w, sB.w); ffma2(a0, sp, wreg[7][0]); ffma2(a1, sp, wreg[7][1]);

            float4 res;
            asm("mov.b64 {%0, %1}, %2;" : "=f"(res.x), "=f"(res.y) : "l"(a0));
            asm("mov.b64 {%0, %1}, %2;" : "=f"(res.z), "=f"(res.w) : "l"(a1));
            res.x = fmaxf(res.x, 0.f);
            res.y = fmaxf(res.y, 0.f);
            res.z = fmaxf(res.z, 0.f);
            res.w = fmaxf(res.w, 0.f);

            const int q   = r >> 4;
            const int hwl = r & 15;
            __stcs(&out4[(size_t)q * 262144 + hwl * 128], res);
        }
    }
}

extern "C" void kernel_launch(void* const* d_in, const int* in_sizes, int n_in,
                              void* d_out, int out_size)
{
    const float* dec  = (const float*)d_in[0];  // (4,20,8,512)
    const float* enc  = (const float*)d_in[1];  // (4,8,16,16,512)
    const float* Wm   = (const float*)d_in[2];  // (8,512)
    const float* bias = (const float*)d_in[3];  // (512,)
    float* out = (float*)d_out;                 // (4,16,8,16,16,512)

    const int smem = 52 * 1024;
    cudaFuncSetAttribute(heatmap_fused,
                         cudaFuncAttributeMaxDynamicSharedMemorySize, smem);

    // 1024 blocks = (b:4)x(t:8)x(hwtile:16)x(qh:2)
    heatmap_fused<<<NB * NT * (NHW / HWT) * 2, 128, smem>>>(dec, enc, Wm, bias, out);
}

// round 11
// speedup vs baseline: 2.6187x; 1.0424x over previous
#include <cuda_runtime.h>

// Problem dims (fixed by the reference setup)
#define NB 4      // batch
#define NQ 16     // queries used (of 20)
#define NQP 20    // queries stored in btn_dec
#define NT 8      // t
#define NHW 256   // h*w
#define HWT 16    // hw positions per block
#define QT 8      // q positions per block (2 halves of 4)
#define NG 8      // heads
#define NF 512    // btn_features

__device__ __forceinline__ void ffma2(unsigned long long& d,
                                      unsigned long long a,
                                      unsigned long long b) {
    asm("fma.rn.f32x2 %0, %1, %2, %0;" : "+l"(d) : "l"(a), "l"(b));
}
__device__ __forceinline__ unsigned long long pack2(float lo, float hi) {
    unsigned long long r;
    asm("mov.b64 %0, {%1, %2};" : "=l"(r) : "f"(lo), "f"(hi));
    return r;
}
__device__ __forceinline__ void unpack2(unsigned long long v, float& lo, float& hi) {
    asm("mov.b64 {%0, %1}, %2;" : "=f"(lo), "=f"(hi) : "l"(v));
}

// Swizzled float4-index within a 512-float row (head g, chunk c4 0..15):
// (c4+g)&15 skew -> conflict-free g-parallel reads, 1-cyc dec broadcasts.
__device__ __forceinline__ int sw_idx(int g, int c4) {
    return g * 16 + ((c4 + g) & 15);
}

// ---------------------------------------------------------------------------
// Fused kernel, software-pipelined. Grid: 1024 blocks =
// (b:4) x (t:8) x (hwtile:16) x (qh:2), 128 threads, 52KB smem -> 4 blk/SM.
//
// Timeline per block:
//   stage enc(32KB)+dec(16KB)            [no stores]
//   A(q0..3) -> sc0                      [no stores]
//   INTERLEAVED: 16 steps, each = 1 c4-step of A(q4..7) (regs only)
//                + 4 B-rows of q0..3 (streaming stores)   <-- stores flow
//   acc -> sc1 ; sync
//   B(q4..7) from sc1                    [stores]
// Stores are active for ~3/4 of block lifetime instead of ~1/2.
// ---------------------------------------------------------------------------
__global__ void __launch_bounds__(128, 4) heatmap_fused(
    const float* __restrict__ dec,   // (4, 20, 8, 512)
    const float* __restrict__ enc,   // (4, 8, 256, 512)
    const float* __restrict__ Wm,    // (8, 512)
    const float* __restrict__ bias,  // (512,)
    float* __restrict__ out)         // (4, 16, 8, 256, 512)
{
    extern __shared__ char smem_raw[];
    ulonglong2* enc_s = reinterpret_cast<ulonglong2*>(smem_raw);            // 32 KB
    ulonglong2* dec_s = reinterpret_cast<ulonglong2*>(smem_raw + 32768);    // 16 KB
    float*      sc0   = reinterpret_cast<float*>(smem_raw + 49152);         //  2 KB
    float*      sc1   = reinterpret_cast<float*>(smem_raw + 51200);         //  2 KB

    const int tid = threadIdx.x;
    const int bid = blockIdx.x;
    const int qh  = bid & 1;             // q half-of-16: q0 = qh*8
    const int hwt = (bid >> 1) & 15;     // hw tile (16 positions)
    const int t   = (bid >> 5) & 7;
    const int b   = bid >> 8;

    // ---- stage enc tile: 16 hw rows x 128 float4, swizzled ----
    {
        const ulonglong2* encg = reinterpret_cast<const ulonglong2*>(enc)
            + ((size_t)((b * NT + t) * NHW + hwt * HWT)) * 128;
#pragma unroll
        for (int k = 0; k < 16; k++) {
            int i = tid + k * 128;           // 0..2047
            int hwl = i >> 7;
            int j   = i & 127;
            enc_s[hwl * 128 + sw_idx(j >> 4, j & 15)] = encg[i];
        }
    }
    // ---- stage dec tile: 8 q rows x 128 float4, swizzled ----
    {
#pragma unroll
        for (int k = 0; k < 8; k++) {
            int i = tid + k * 128;           // 0..1023
            int q = i >> 7;                  // local q 0..7
            int j = i & 127;
            const ulonglong2* decg = reinterpret_cast<const ulonglong2*>(dec)
                + ((size_t)((b * NQP + qh * QT + q) * NT + t)) * 128;
            dec_s[q * 128 + sw_idx(j >> 4, j & 15)] = decg[j];
        }
    }
    __syncthreads();

    // Phase-A thread mapping (persistent across both halves)
    const int ga  = tid & 7;
    const int hwa = tid >> 3;               // 0..15
    const ulonglong2* erow = enc_s + hwa * 128;

    // ---- A(q0..3) -> sc0 ----
    {
        unsigned long long acc[4];
#pragma unroll
        for (int q = 0; q < 4; q++) acc[q] = 0ull;
#pragma unroll 4
        for (int c4 = 0; c4 < 16; c4++) {
            const int cc = sw_idx(ga, c4);
            ulonglong2 e = erow[cc];
#pragma unroll
            for (int q = 0; q < 4; q++) {
                ulonglong2 d = dec_s[q * 128 + cc];
                ffma2(acc[q], e.x, d.x);
                ffma2(acc[q], e.y, d.y);
            }
        }
#pragma unroll
        for (int q = 0; q < 4; q++) {
            float lo, hi;
            unpack2(acc[q], lo, hi);
            sc0[(q * HWT + hwa) * NG + ga] = lo + hi;
        }
    }

    // W/bias into registers (overlaps phase-A tail)
    const int f4 = tid;
    const unsigned long long* W2 = reinterpret_cast<const unsigned long long*>(Wm);
    unsigned long long wreg[NG][2];
#pragma unroll
    for (int g = 0; g < NG; g++) {
        wreg[g][0] = W2[g * 256 + f4 * 2];
        wreg[g][1] = W2[g * 256 + f4 * 2 + 1];
    }
    const unsigned long long* B2 = reinterpret_cast<const unsigned long long*>(bias);
    const unsigned long long bb0 = B2[f4 * 2];
    const unsigned long long bb1 = B2[f4 * 2 + 1];

    __syncthreads();

    // out float4 base: (((b*16 + qh*8)*8+t)*256 + hwt*16)*128 + f4
    float4* out4 = reinterpret_cast<float4*>(out)
        + ((size_t)((b * NQ + qh * QT) * NT + t) * NHW + hwt * HWT) * 128 + f4;
    // local q stride (float4): 8*256*128 = 262144 ; hwl stride: 128

#define B_ROW(scf, r, qofs)                                                        \
    {                                                                              \
        float4 sA = (scf)[(r) * 2 + 0];                                            \
        float4 sB = (scf)[(r) * 2 + 1];                                            \
        unsigned long long a0 = bb0, a1 = bb1;                                     \
        unsigned long long sp;                                                     \
        sp = pack2(sA.x, sA.x); ffma2(a0, sp, wreg[0][0]); ffma2(a1, sp, wreg[0][1]); \
        sp = pack2(sA.y, sA.y); ffma2(a0, sp, wreg[1][0]); ffma2(a1, sp, wreg[1][1]); \
        sp = pack2(sA.z, sA.z); ffma2(a0, sp, wreg[2][0]); ffma2(a1, sp, wreg[2][1]); \
        sp = pack2(sA.w, sA.w); ffma2(a0, sp, wreg[3][0]); ffma2(a1, sp, wreg[3][1]); \
        sp = pack2(sB.x, sB.x); ffma2(a0, sp, wreg[4][0]); ffma2(a1, sp, wreg[4][1]); \
        sp = pack2(sB.y, sB.y); ffma2(a0, sp, wreg[5][0]); ffma2(a1, sp, wreg[5][1]); \
        sp = pack2(sB.z, sB.z); ffma2(a0, sp, wreg[6][0]); ffma2(a1, sp, wreg[6][1]); \
        sp = pack2(sB.w, sB.w); ffma2(a0, sp, wreg[7][0]); ffma2(a1, sp, wreg[7][1]); \
        float4 res;                                                                \
        asm("mov.b64 {%0, %1}, %2;" : "=f"(res.x), "=f"(res.y) : "l"(a0));         \
        asm("mov.b64 {%0, %1}, %2;" : "=f"(res.z), "=f"(res.w) : "l"(a1));         \
        res.x = fmaxf(res.x, 0.f);                                                 \
        res.y = fmaxf(res.y, 0.f);                                                 \
        res.z = fmaxf(res.z, 0.f);                                                 \
        res.w = fmaxf(res.w, 0.f);                                                 \
        const int q_   = ((r) >> 4) + (qofs);                                      \
        const int hwl_ = (r) & 15;                                                 \
        __stcs(&out4[(size_t)q_ * 262144 + hwl_ * 128], res);                      \
    }

    // ---- INTERLEAVED: A(q4..7) c4-steps woven between B(q0..3) rows ----
    {
        unsigned long long acc2[4];
#pragma unroll
        for (int q = 0; q < 4; q++) acc2[q] = 0ull;

        const float4* scf0 = reinterpret_cast<const float4*>(sc0);

#pragma unroll 2
        for (int s = 0; s < 16; s++) {
            // one c4-step of A(q4..7) — registers only
            const int cc = sw_idx(ga, s);
            ulonglong2 e = erow[cc];
#pragma unroll
            for (int q = 0; q < 4; q++) {
                ulonglong2 d = dec_s[(4 + q) * 128 + cc];
                ffma2(acc2[q], e.x, d.x);
                ffma2(acc2[q], e.y, d.y);
            }
            // four B rows of q0..3 — streaming stores
#pragma unroll
            for (int rr = 0; rr < 4; rr++) {
                B_ROW(scf0, s * 4 + rr, 0);
            }
        }

        // flush A(q4..7) accumulators to the second score buffer
#pragma unroll
        for (int q = 0; q < 4; q++) {
            float lo, hi;
            unpack2(acc2[q], lo, hi);
            sc1[(q * HWT + hwa) * NG + ga] = lo + hi;
        }
    }
    __syncthreads();

    // ---- B(q4..7) from sc1 ----
    {
        const float4* scf1 = reinterpret_cast<const float4*>(sc1);
#pragma unroll 4
        for (int r = 0; r < 64; r++) {
            B_ROW(scf1, r, 4);
        }
    }
#undef B_ROW
}

extern "C" void kernel_launch(void* const* d_in, const int* in_sizes, int n_in,
                              void* d_out, int out_size)
{
    const float* dec  = (const float*)d_in[0];  // (4,20,8,512)
    const float* enc  = (const float*)d_in[1];  // (4,8,16,16,512)
    const float* Wm   = (const float*)d_in[2];  // (8,512)
    const float* bias = (const float*)d_in[3];  // (512,)
    float* out = (float*)d_out;                 // (4,16,8,16,16,512)

    const int smem = 52 * 1024;
    cudaFuncSetAttribute(heatmap_fused,
                         cudaFuncAttributeMaxDynamicSharedMemorySize, smem);

    // 1024 blocks = (b:4)x(t:8)x(hwtile:16)x(qh:2)
    heatmap_fused<<<NB * NT * (NHW / HWT) * 2, 128, smem>>>(dec, enc, Wm, bias, out);
}